// round 10
// baseline (speedup 1.0000x reference)
#include <cuda_runtime.h>
#include <cuda_fp16.h>
#include <cstdint>

#define N 8192
#define D 128
#define NUM_CLASSES 256
#define MARGIN 0.3f

#define BM 128
#define BN 128
#define BKP 40                        // padded row: 80B = 20 banks, ldmatrix conflict-free
#define CHUNK_ELEMS (128 * BKP)       // 5120 fp16 per (rowblock, kchunk)
#define CHUNK_BYTES (CHUNK_ELEMS * 2) // 10240 B
#define STAGE_BYTES (2 * CHUNK_BYTES) // A, B = 20480 B
#define SMEM_DATA   (2 * STAGE_BYTES) // double buffered = 40960 B
#define SMEM_TOTAL  (SMEM_DATA + 16)  // + 2 mbarriers

// Persistent device state (module globals; no allocation).
__device__ float    g_sq[N];
__device__ int      g_cls[N];
__device__ float    g_pos_sum[N];
__device__ float    g_neg_sum[N];
__device__ unsigned g_pos_max[N];     // float bits; dsq > 0 so uint order == float order
__device__ unsigned g_neg_min[N];
__device__ int      g_hist[NUM_CLASSES];
// tile-major, pre-padded: [block 0..63][kchunk 0..3][row 0..127 * BKP + col]
__device__ __align__(16) __half g_xh[N * 4 * BKP];

__device__ __forceinline__ unsigned su32(const void* p) {
    return (unsigned)__cvta_generic_to_shared(p);
}

#define LDMX4(r0, r1, r2, r3, addr)                                         \
    asm volatile("ldmatrix.sync.aligned.m8n8.x4.shared.b16 {%0,%1,%2,%3}, [%4];" \
                 : "=r"(r0), "=r"(r1), "=r"(r2), "=r"(r3) : "r"(addr))

#define MMA_F16(c0, c1, c2, c3, a, b)                                       \
    asm volatile("mma.sync.aligned.m16n8k16.row.col.f32.f16.f16.f32 "       \
                 "{%0,%1,%2,%3}, {%4,%5,%6,%7}, {%8,%9}, {%0,%1,%2,%3};"    \
                 : "+f"(c0), "+f"(c1), "+f"(c2), "+f"(c3)                    \
                 : "r"((a)[0]), "r"((a)[1]), "r"((a)[2]), "r"((a)[3]),       \
                   "r"((b)[0]), "r"((b)[1]))

__device__ __forceinline__ void mbar_wait(unsigned mbar, unsigned parity) {
    asm volatile("{\n\t.reg .pred P;\n\t"
                 "WL%=:\n\t"
                 "mbarrier.try_wait.parity.acquire.cta.shared::cta.b64 P, [%0], %1, 0x989680;\n\t"
                 "@P bra WD%=;\n\t"
                 "bra WL%=;\n\t"
                 "WD%=:\n\t}"
                 :: "r"(mbar), "r"(parity) : "memory");
}

// ---------------------------------------------------------------------------
// Kernel 1: warp-per-row. Squared norms (fp32) + fp16 cast of X written in the
// padded tile-major layout so dist_kernel can bulk-copy chunks verbatim.
// ---------------------------------------------------------------------------
__global__ void prep_kernel(const float* __restrict__ x)
{
    int gt   = blockIdx.x * blockDim.x + threadIdx.x;
    int row  = gt >> 5;
    int lane = gt & 31;
    if (row >= N) return;

    float4 v = ((const float4*)(x + (size_t)row * D))[lane];
    float s = v.x * v.x + v.y * v.y + v.z * v.z + v.w * v.w;
    #pragma unroll
    for (int o = 16; o; o >>= 1) s += __shfl_xor_sync(0xffffffffu, s, o);
    if (lane == 0) g_sq[row] = s;

    float f[4] = {v.x, v.y, v.z, v.w};
    unsigned short h[4];
    #pragma unroll
    for (int k = 0; k < 4; k++)
        h[k] = __half_as_ushort(__float2half_rn(f[k]));
    uint2 uh;
    uh.x = (unsigned)h[0] | ((unsigned)h[1] << 16);
    uh.y = (unsigned)h[2] | ((unsigned)h[3] << 16);

    int blk = row >> 7, r = row & 127;
    size_t off = (size_t)(blk * 4 + (lane >> 3)) * CHUNK_ELEMS + r * BKP + (lane & 7) * 4;
    *(uint2*)(g_xh + off) = uh;
}

// ---------------------------------------------------------------------------
// Kernel 2: targets (dtype auto-detect) + accumulator/hist/out reset.
// ---------------------------------------------------------------------------
__global__ void init2_kernel(const void* __restrict__ tgt, int tgt_elems,
                             float* __restrict__ out)
{
    __shared__ int s_is64;
    if (threadIdx.x == 0) {
        const long long* t64 = (const long long*)tgt;
        int is64 = 1;
        int probe = tgt_elems < 8 ? tgt_elems : 8;
        for (int i = 0; i < probe; i++) {
            long long v = t64[i];
            if (v < 0 || v >= NUM_CLASSES) { is64 = 0; break; }
        }
        s_is64 = is64;
    }
    __syncthreads();
    int r = blockIdx.x * blockDim.x + threadIdx.x;
    if (r < N) {
        int c;
        if (s_is64) c = (int)((const long long*)tgt)[r];
        else        c = ((const int*)tgt)[r];
        g_cls[r]     = c;
        g_pos_sum[r] = 0.f;
        g_neg_sum[r] = 0.f;
        g_pos_max[r] = 0u;
        g_neg_min[r] = 0x7F800000u;
    }
    if (r < NUM_CLASSES) g_hist[r] = 0;
    if (r == 0) out[0] = 0.f;
}

__global__ void hist_kernel()
{
    int r = blockIdx.x * blockDim.x + threadIdx.x;
    if (r < N) atomicAdd(&g_hist[g_cls[r]], 1);
}

// ---------------------------------------------------------------------------
// Kernel 3: triangular tiled X*X^T, fp16 mma.sync, cp.async.bulk double
// buffering. 512 threads, 4x4 warp grid, 32x32 warp tiles for occupancy.
// ---------------------------------------------------------------------------
__device__ __forceinline__ void issue_stage(unsigned sbase, int s, int kb,
                                            int by, int bx)
{
    unsigned mbar = sbase + SMEM_DATA + s * 8;
    asm volatile("mbarrier.arrive.expect_tx.shared.b64 _, [%0], %1;"
                 :: "r"(mbar), "r"((unsigned)STAGE_BYTES) : "memory");
    const __half* srcs[2] = {
        g_xh + (size_t)(by * 4 + kb) * CHUNK_ELEMS,
        g_xh + (size_t)(bx * 4 + kb) * CHUNK_ELEMS
    };
    #pragma unroll
    for (int o = 0; o < 2; o++) {
        unsigned dst = sbase + (unsigned)(s * 2 + o) * CHUNK_BYTES;
        asm volatile("cp.async.bulk.shared::cluster.global.mbarrier::complete_tx::bytes "
                     "[%0], [%1], %2, [%3];"
                     :: "r"(dst), "l"(srcs[o]), "r"((unsigned)CHUNK_BYTES), "r"(mbar)
                     : "memory");
    }
}

__global__ __launch_bounds__(512, 2) void dist_kernel()
{
    const int bx = blockIdx.x, by = blockIdx.y;
    if (bx < by) return;
    const bool offdiag = (bx != by);
    const int i0 = by * BM, j0 = bx * BN;

    extern __shared__ char smem[];
    const unsigned sbase = su32(smem);

    __shared__ float    r_psum[BM], r_nsum[BM];
    __shared__ unsigned r_pmax[BM], r_nmin[BM];
    __shared__ float    c_psum[BN], c_nsum[BN];
    __shared__ unsigned c_pmax[BN], c_nmin[BN];
    __shared__ float    s_sqi[BM], s_sqj[BN];
    __shared__ int      s_clsi[BM], s_clsj[BN];

    const int tid = threadIdx.x;
    const int wid = tid >> 5, lane = tid & 31;
    const int warp_m = (wid >> 2) * 32;   // 0,32,64,96
    const int warp_n = (wid & 3) * 32;    // 0,32,64,96

    if (tid < BM) {
        r_psum[tid] = 0.f; r_nsum[tid] = 0.f; r_pmax[tid] = 0u; r_nmin[tid] = 0x7F800000u;
        c_psum[tid] = 0.f; c_nsum[tid] = 0.f; c_pmax[tid] = 0u; c_nmin[tid] = 0x7F800000u;
        s_sqi[tid]  = g_sq[i0 + tid];
        s_clsi[tid] = g_cls[i0 + tid];
    } else if (tid < 2 * BM) {
        int c = tid - BM;
        s_sqj[c]  = g_sq[j0 + c];
        s_clsj[c] = g_cls[j0 + c];
    }
    if (tid == 0) {
        asm volatile("mbarrier.init.shared.b64 [%0], %1;"
                     :: "r"(sbase + SMEM_DATA), "r"(1u) : "memory");
        asm volatile("mbarrier.init.shared.b64 [%0], %1;"
                     :: "r"(sbase + SMEM_DATA + 8), "r"(1u) : "memory");
    }
    __syncthreads();
    if (tid == 0) {
        issue_stage(sbase, 0, 0, by, bx);
        issue_stage(sbase, 1, 1, by, bx);
    }

    float C[4][8];
    #pragma unroll
    for (int a = 0; a < 4; a++)
        #pragma unroll
        for (int b = 0; b < 8; b++) C[a][b] = 0.f;

    // per-lane ldmatrix byte offsets (80B row pitch)
    const unsigned aoff = (unsigned)(lane & 15) * (BKP * 2) + (unsigned)(lane >> 4) * 16
                        + (unsigned)warp_m * (BKP * 2);
    const unsigned boff = (unsigned)(((lane >> 4) & 1) * 8 + (lane & 7)) * (BKP * 2)
                        + (unsigned)((lane >> 3) & 1) * 16
                        + (unsigned)warp_n * (BKP * 2);

    for (int kb = 0; kb < 4; kb++) {
        const int s = kb & 1;
        mbar_wait(sbase + SMEM_DATA + s * 8, (unsigned)(kb >> 1));

        const unsigned sb = sbase + (unsigned)s * STAGE_BYTES;
        const unsigned aA = sb + aoff;
        const unsigned aB = sb + CHUNK_BYTES + boff;

        #pragma unroll
        for (int ks = 0; ks < 2; ks++) {
            const unsigned kbyte = (unsigned)ks * 32;  // 16 fp16 = 32B
            unsigned A[2][4], B[4][2];
            #pragma unroll
            for (int mt = 0; mt < 2; mt++) {
                const unsigned moff = (unsigned)(mt * 16) * (BKP * 2) + kbyte;
                LDMX4(A[mt][0], A[mt][1], A[mt][2], A[mt][3], aA + moff);
            }
            #pragma unroll
            for (int bq = 0; bq < 2; bq++) {
                const unsigned noff = (unsigned)(bq * 16) * (BKP * 2) + kbyte;
                unsigned r0, r1, r2, r3;
                LDMX4(r0, r1, r2, r3, aB + noff);
                B[2 * bq][0] = r0; B[2 * bq][1] = r1;
                B[2 * bq + 1][0] = r2; B[2 * bq + 1][1] = r3;
            }
            #pragma unroll
            for (int mt = 0; mt < 2; mt++)
                #pragma unroll
                for (int nt = 0; nt < 4; nt++)
                    MMA_F16(C[2*mt][2*nt], C[2*mt][2*nt+1], C[2*mt+1][2*nt], C[2*mt+1][2*nt+1],
                            A[mt], B[nt]);
        }
        __syncthreads();                 // all warps done reading stage s
        if (tid == 0 && kb < 2) issue_stage(sbase, s, kb + 2, by, bx);
    }

    // ---- epilogue (metadata from smem; 32 elements per thread) ----
    const int rg = lane >> 2, cg = lane & 3;

    // row pass: convert dot->dsq in place, reduce over this thread's 8 cols,
    // then quad shuffle across the 4 cg lanes.
    #pragma unroll
    for (int mi = 0; mi < 4; mi++) {
        const int lr   = warp_m + (mi >> 1) * 16 + (mi & 1) * 8 + rg;
        const float si = s_sqi[lr];
        const int   ki = s_clsi[lr];
        const int   gi = i0 + lr;
        float psum = 0.f, nsum = 0.f;
        float pmax = 0.f, nmin = __uint_as_float(0x7F800000u);
        #pragma unroll
        for (int ci = 0; ci < 8; ci++) {
            const int lc = warp_n + (ci >> 1) * 8 + 2 * cg + (ci & 1);
            float dsq = fmaxf(si + s_sqj[lc] - 2.f * C[mi][ci], 1e-12f);
            C[mi][ci] = dsq;
            if (ki == s_clsj[lc]) {
                if (gi != j0 + lc) {       // reference drops the self element
                    psum += dsq;
                    pmax  = fmaxf(pmax, dsq);
                }
            } else {
                nsum += dsq;
                nmin  = fminf(nmin, dsq);
            }
        }
        #pragma unroll
        for (int o = 1; o <= 2; o <<= 1) {
            psum += __shfl_xor_sync(0xffffffffu, psum, o);
            nsum += __shfl_xor_sync(0xffffffffu, nsum, o);
            pmax  = fmaxf(pmax, __shfl_xor_sync(0xffffffffu, pmax, o));
            nmin  = fminf(nmin, __shfl_xor_sync(0xffffffffu, nmin, o));
        }
        if (cg == 0) {
            atomicAdd(&r_psum[lr], psum);
            atomicAdd(&r_nsum[lr], nsum);
            atomicMax(&r_pmax[lr], __float_as_uint(pmax));
            atomicMin(&r_nmin[lr], __float_as_uint(nmin));
        }
    }

    // column pass (symmetry: row-j reductions) for off-diagonal tiles
    if (offdiag) {
        #pragma unroll
        for (int ci = 0; ci < 8; ci++) {
            const int lc = warp_n + (ci >> 1) * 8 + 2 * cg + (ci & 1);
            const int kj = s_clsj[lc];
            float psum = 0.f, nsum = 0.f;
            float pmax = 0.f, nmin = __uint_as_float(0x7F800000u);
            #pragma unroll
            for (int mi = 0; mi < 4; mi++) {
                const int lr = warp_m + (mi >> 1) * 16 + (mi & 1) * 8 + rg;
                float dsq = C[mi][ci];
                if (s_clsi[lr] == kj) {
                    psum += dsq;
                    pmax  = fmaxf(pmax, dsq);
                } else {
                    nsum += dsq;
                    nmin  = fminf(nmin, dsq);
                }
            }
            #pragma unroll
            for (int o = 4; o <= 16; o <<= 1) {
                psum += __shfl_xor_sync(0xffffffffu, psum, o);
                nsum += __shfl_xor_sync(0xffffffffu, nsum, o);
                pmax  = fmaxf(pmax, __shfl_xor_sync(0xffffffffu, pmax, o));
                nmin  = fminf(nmin, __shfl_xor_sync(0xffffffffu, nmin, o));
            }
            if (lane < 4) {
                atomicAdd(&c_psum[lc], psum);
                atomicAdd(&c_nsum[lc], nsum);
                atomicMax(&c_pmax[lc], __float_as_uint(pmax));
                atomicMin(&c_nmin[lc], __float_as_uint(nmin));
            }
        }
    }

    __syncthreads();
    if (tid < BM) {
        int i = i0 + tid;
        atomicAdd(&g_pos_sum[i], r_psum[tid]);
        atomicAdd(&g_neg_sum[i], r_nsum[tid]);
        atomicMax(&g_pos_max[i], r_pmax[tid]);
        atomicMin(&g_neg_min[i], r_nmin[tid]);
        if (offdiag) {
            int j = j0 + tid;
            atomicAdd(&g_pos_sum[j], c_psum[tid]);
            atomicAdd(&g_neg_sum[j], c_nsum[tid]);
            atomicMax(&g_pos_max[j], c_pmax[tid]);
            atomicMin(&g_neg_min[j], c_nmin[tid]);
        }
    }
}

// ---------------------------------------------------------------------------
// Kernel 4: per-row loss terms + mean. 32 blocks; one atomicAdd per block.
// ---------------------------------------------------------------------------
__global__ void finalize_kernel(float* __restrict__ out)
{
    __shared__ float red[256];
    const int tid = threadIdx.x;
    const int r   = blockIdx.x * 256 + tid;

    int   h       = g_hist[g_cls[r]];
    float cnt_p   = (float)(h - 1);
    float cnt_n   = (float)(N - h);
    float sigma_p = g_pos_sum[r] / cnt_p;
    float sigma_n = g_neg_sum[r] / cnt_n;
    float ap = __uint_as_float(g_pos_max[r]) / sigma_p + 0.5f * logf(sigma_p);
    float an = __uint_as_float(g_neg_min[r]) / sigma_n + 0.5f * logf(sigma_n);
    float lsum = fmaxf(ap - an + MARGIN, 0.f);

    red[tid] = lsum;
    __syncthreads();
    #pragma unroll
    for (int s = 128; s > 0; s >>= 1) {
        if (tid < s) red[tid] += red[tid + s];
        __syncthreads();
    }
    if (tid == 0) atomicAdd(out, red[0] * (1.f / (float)N));
}

// ---------------------------------------------------------------------------
extern "C" void kernel_launch(void* const* d_in, const int* in_sizes, int n_in,
                              void* d_out, int out_size)
{
    const float* x = (const float*)d_in[0];
    const void*  t = d_in[1];
    int tgt_elems = (n_in > 1) ? in_sizes[1] : N;

    cudaFuncSetAttribute(dist_kernel, cudaFuncAttributeMaxDynamicSharedMemorySize,
                         SMEM_TOTAL);

    prep_kernel<<<N / 8, 256>>>(x);
    init2_kernel<<<(N + 255) / 256, 256>>>(t, tgt_elems, (float*)d_out);
    hist_kernel<<<(N + 255) / 256, 256>>>();
    dist_kernel<<<dim3(64, 64), 512, SMEM_TOTAL>>>();
    finalize_kernel<<<N / 256, 256>>>((float*)d_out);
}

// round 11
// speedup vs baseline: 1.0378x; 1.0378x over previous
#include <cuda_runtime.h>
#include <cuda_fp16.h>
#include <cstdint>

#define N 8192
#define D 128
#define NUM_CLASSES 256
#define MARGIN 0.3f

#define BM 128
#define BN 128

// Persistent device state (module globals; no allocation).
__device__ float    g_sq[N];
__device__ int      g_cls[N];
__device__ float    g_pos_sum[N];
__device__ float    g_neg_sum[N];
__device__ unsigned g_pos_max[N];     // float bits; dsq > 0 so uint order == float order
__device__ unsigned g_neg_min[N];
__device__ int      g_hist[NUM_CLASSES];
// Fragment-major fp16 copy of X: [rowblock16 0..511][kstep 0..7][lane 0..31] x 16B.
// Lane L (g=L>>2, t=L&3) holds {X[rb16+g][2t,2t+1], X[rb16+8+g][2t,2t+1],
//                               X[rb16+g][2t+8,2t+9], X[rb16+8+g][2t+8,2t+9]}
// (cols relative to kstep*16) = mma.m16n8k16 A regs {a0,a1,a2,a3}.
// B fragments are a permutation: B_lo = {a0,a2} (rows +0..7), B_hi = {a1,a3} (rows +8..15).
__device__ __align__(16) uint4 g_fx[512 * 8 * 32];

#define MMA_F16(c0, c1, c2, c3, a, b)                                       \
    asm volatile("mma.sync.aligned.m16n8k16.row.col.f32.f16.f16.f32 "       \
                 "{%0,%1,%2,%3}, {%4,%5,%6,%7}, {%8,%9}, {%0,%1,%2,%3};"    \
                 : "+f"(c0), "+f"(c1), "+f"(c2), "+f"(c3)                    \
                 : "r"((a)[0]), "r"((a)[1]), "r"((a)[2]), "r"((a)[3]),       \
                   "r"((b)[0]), "r"((b)[1]))

// ---------------------------------------------------------------------------
// Kernel 1: warp-per-row squared norms (fp32).
// ---------------------------------------------------------------------------
__global__ void prep_kernel(const float* __restrict__ x)
{
    int gt   = blockIdx.x * blockDim.x + threadIdx.x;
    int row  = gt >> 5;
    int lane = gt & 31;
    if (row >= N) return;

    float4 v = ((const float4*)(x + (size_t)row * D))[lane];
    float s = v.x * v.x + v.y * v.y + v.z * v.z + v.w * v.w;
    #pragma unroll
    for (int o = 16; o; o >>= 1) s += __shfl_xor_sync(0xffffffffu, s, o);
    if (lane == 0) g_sq[row] = s;
}

// ---------------------------------------------------------------------------
// Kernel 2: fragment packer (one warp per (rowblock16, kstep)) + hist/out zero.
// ---------------------------------------------------------------------------
__global__ void pack_kernel(const float* __restrict__ x, float* __restrict__ out)
{
    const int tid  = threadIdx.x;
    const int w    = blockIdx.x * 8 + (tid >> 5);   // 0..4095
    const int lane = tid & 31;
    const int rb   = w >> 3, ks = w & 7;
    const int g    = lane >> 2, t = lane & 3;

    const int r0 = rb * 16 + g, r1 = r0 + 8;
    const int c0 = ks * 16 + 2 * t, c2 = c0 + 8;

    float2 f0 = *(const float2*)(x + (size_t)r0 * D + c0);
    float2 f1 = *(const float2*)(x + (size_t)r1 * D + c0);
    float2 f2 = *(const float2*)(x + (size_t)r0 * D + c2);
    float2 f3 = *(const float2*)(x + (size_t)r1 * D + c2);

    uint4 v;
    v.x = (unsigned)__half_as_ushort(__float2half_rn(f0.x))
        | ((unsigned)__half_as_ushort(__float2half_rn(f0.y)) << 16);
    v.y = (unsigned)__half_as_ushort(__float2half_rn(f1.x))
        | ((unsigned)__half_as_ushort(__float2half_rn(f1.y)) << 16);
    v.z = (unsigned)__half_as_ushort(__float2half_rn(f2.x))
        | ((unsigned)__half_as_ushort(__float2half_rn(f2.y)) << 16);
    v.w = (unsigned)__half_as_ushort(__float2half_rn(f3.x))
        | ((unsigned)__half_as_ushort(__float2half_rn(f3.y)) << 16);

    g_fx[w * 32 + lane] = v;

    if (blockIdx.x == 0) {
        if (tid < NUM_CLASSES) g_hist[tid] = 0;
        if (tid == 0) out[0] = 0.f;
    }
}

// ---------------------------------------------------------------------------
// Kernel 3: targets (dtype auto-detect) + accumulator resets + histogram.
// (g_hist zeroed in the preceding pack_kernel launch.)
// ---------------------------------------------------------------------------
__global__ void init2_kernel(const void* __restrict__ tgt, int tgt_elems)
{
    __shared__ int s_is64;
    if (threadIdx.x == 0) {
        const long long* t64 = (const long long*)tgt;
        int is64 = 1;
        int probe = tgt_elems < 8 ? tgt_elems : 8;
        for (int i = 0; i < probe; i++) {
            long long v = t64[i];
            if (v < 0 || v >= NUM_CLASSES) { is64 = 0; break; }
        }
        s_is64 = is64;
    }
    __syncthreads();
    int r = blockIdx.x * blockDim.x + threadIdx.x;
    if (r < N) {
        int c;
        if (s_is64) c = (int)((const long long*)tgt)[r];
        else        c = ((const int*)tgt)[r];
        g_cls[r]     = c;
        g_pos_sum[r] = 0.f;
        g_neg_sum[r] = 0.f;
        g_pos_max[r] = 0u;
        g_neg_min[r] = 0x7F800000u;
        atomicAdd(&g_hist[c], 1);
    }
}

// ---------------------------------------------------------------------------
// Kernel 4: triangular tiled X*X^T, fragment-direct LDG + fp16 mma.sync.
// 256 threads, 2x4 warp grid, 64x32 warp tiles. No smem staging, no syncs
// in the mainloop.
// ---------------------------------------------------------------------------
__global__ __launch_bounds__(256, 2) void dist_kernel()
{
    const int bx = blockIdx.x, by = blockIdx.y;
    if (bx < by) return;
    const bool offdiag = (bx != by);
    const int i0 = by * BM, j0 = bx * BN;

    __shared__ float    r_psum[BM], r_nsum[BM];
    __shared__ unsigned r_pmax[BM], r_nmin[BM];
    __shared__ float    c_psum[BN], c_nsum[BN];
    __shared__ unsigned c_pmax[BN], c_nmin[BN];
    __shared__ float    s_sqi[BM], s_sqj[BN];
    __shared__ int      s_clsi[BM], s_clsj[BN];

    const int tid = threadIdx.x;
    const int wid = tid >> 5, lane = tid & 31;
    const int warp_m = (wid >> 2) * 64;   // 0 or 64
    const int warp_n = (wid & 3) * 32;    // 0,32,64,96

    if (tid < BM) {
        r_psum[tid] = 0.f; r_nsum[tid] = 0.f; r_pmax[tid] = 0u; r_nmin[tid] = 0x7F800000u;
        c_psum[tid] = 0.f; c_nsum[tid] = 0.f; c_pmax[tid] = 0u; c_nmin[tid] = 0x7F800000u;
        s_sqi[tid]  = g_sq[i0 + tid];
        s_clsi[tid] = g_cls[i0 + tid];
    } else {
        int c = tid - BM;
        s_sqj[c]  = g_sq[j0 + c];
        s_clsj[c] = g_cls[j0 + c];
    }
    __syncthreads();

    const int ib = (i0 >> 4) + (warp_m >> 4);   // rowblock16 base for this warp
    const int jb = (j0 >> 4) + (warp_n >> 4);   // colblock16 base for this warp

    // per-(block16) fragment pointers; ks stride = 32 uint4 = 512B (imm offset)
    const uint4* pA0 = g_fx + (size_t)(ib + 0) * 256 + lane;
    const uint4* pA1 = g_fx + (size_t)(ib + 1) * 256 + lane;
    const uint4* pA2 = g_fx + (size_t)(ib + 2) * 256 + lane;
    const uint4* pA3 = g_fx + (size_t)(ib + 3) * 256 + lane;
    const uint4* pB0 = g_fx + (size_t)(jb + 0) * 256 + lane;
    const uint4* pB1 = g_fx + (size_t)(jb + 1) * 256 + lane;

    float C[8][8];
    #pragma unroll
    for (int a = 0; a < 8; a++)
        #pragma unroll
        for (int b = 0; b < 8; b++) C[a][b] = 0.f;

    #pragma unroll 2
    for (int ks = 0; ks < 8; ks++) {
        uint4 va[4], vb[2];
        va[0] = pA0[ks * 32];
        va[1] = pA1[ks * 32];
        va[2] = pA2[ks * 32];
        va[3] = pA3[ks * 32];
        vb[0] = pB0[ks * 32];
        vb[1] = pB1[ks * 32];

        #pragma unroll
        for (int cb = 0; cb < 2; cb++) {
            unsigned Blo[2] = {vb[cb].x, vb[cb].z};
            unsigned Bhi[2] = {vb[cb].y, vb[cb].w};
            #pragma unroll
            for (int mt = 0; mt < 4; mt++) {
                unsigned Af[4] = {va[mt].x, va[mt].y, va[mt].z, va[mt].w};
                const int nlo = 2 * (2 * cb);       // cols warp_n + cb*16 + 0..7
                const int nhi = 2 * (2 * cb + 1);   // cols warp_n + cb*16 + 8..15
                MMA_F16(C[2*mt][nlo], C[2*mt][nlo+1], C[2*mt+1][nlo], C[2*mt+1][nlo+1],
                        Af, Blo);
                MMA_F16(C[2*mt][nhi], C[2*mt][nhi+1], C[2*mt+1][nhi], C[2*mt+1][nhi+1],
                        Af, Bhi);
            }
        }
    }

    // ---- epilogue (metadata from smem) ----
    const int rg = lane >> 2, cg = lane & 3;

    // row pass: convert dot->dsq in place, reduce this thread's 8 cols, quad shuffle
    #pragma unroll
    for (int mi = 0; mi < 8; mi++) {
        const int lr   = warp_m + (mi >> 1) * 16 + (mi & 1) * 8 + rg;
        const float si = s_sqi[lr];
        const int   ki = s_clsi[lr];
        const int   gi = i0 + lr;
        float psum = 0.f, nsum = 0.f;
        float pmax = 0.f, nmin = __uint_as_float(0x7F800000u);
        #pragma unroll
        for (int ci = 0; ci < 8; ci++) {
            const int lc = warp_n + (ci >> 1) * 8 + 2 * cg + (ci & 1);
            float dsq = fmaxf(si + s_sqj[lc] - 2.f * C[mi][ci], 1e-12f);
            C[mi][ci] = dsq;
            if (ki == s_clsj[lc]) {
                if (gi != j0 + lc) {       // reference drops the self element
                    psum += dsq;
                    pmax  = fmaxf(pmax, dsq);
                }
            } else {
                nsum += dsq;
                nmin  = fminf(nmin, dsq);
            }
        }
        #pragma unroll
        for (int o = 1; o <= 2; o <<= 1) {
            psum += __shfl_xor_sync(0xffffffffu, psum, o);
            nsum += __shfl_xor_sync(0xffffffffu, nsum, o);
            pmax  = fmaxf(pmax, __shfl_xor_sync(0xffffffffu, pmax, o));
            nmin  = fminf(nmin, __shfl_xor_sync(0xffffffffu, nmin, o));
        }
        if (cg == 0) {
            atomicAdd(&r_psum[lr], psum);
            atomicAdd(&r_nsum[lr], nsum);
            atomicMax(&r_pmax[lr], __float_as_uint(pmax));
            atomicMin(&r_nmin[lr], __float_as_uint(nmin));
        }
    }

    // column pass (symmetry: row-j reductions) for off-diagonal tiles
    if (offdiag) {
        #pragma unroll
        for (int ci = 0; ci < 8; ci++) {
            const int lc = warp_n + (ci >> 1) * 8 + 2 * cg + (ci & 1);
            const int kj = s_clsj[lc];
            float psum = 0.f, nsum = 0.f;
            float pmax = 0.f, nmin = __uint_as_float(0x7F800000u);
            #pragma unroll
            for (int mi = 0; mi < 8; mi++) {
                const int lr = warp_m + (mi >> 1) * 16 + (mi & 1) * 8 + rg;
                float dsq = C[mi][ci];
                if (s_clsi[lr] == kj) {
                    psum += dsq;
                    pmax  = fmaxf(pmax, dsq);
                } else {
                    nsum += dsq;
                    nmin  = fminf(nmin, dsq);
                }
            }
            #pragma unroll
            for (int o = 4; o <= 16; o <<= 1) {
                psum += __shfl_xor_sync(0xffffffffu, psum, o);
                nsum += __shfl_xor_sync(0xffffffffu, nsum, o);
                pmax  = fmaxf(pmax, __shfl_xor_sync(0xffffffffu, pmax, o));
                nmin  = fminf(nmin, __shfl_xor_sync(0xffffffffu, nmin, o));
            }
            if (lane < 4) {
                atomicAdd(&c_psum[lc], psum);
                atomicAdd(&c_nsum[lc], nsum);
                atomicMax(&c_pmax[lc], __float_as_uint(pmax));
                atomicMin(&c_nmin[lc], __float_as_uint(nmin));
            }
        }
    }

    __syncthreads();
    if (tid < BM) {
        int i = i0 + tid;
        atomicAdd(&g_pos_sum[i], r_psum[tid]);
        atomicAdd(&g_neg_sum[i], r_nsum[tid]);
        atomicMax(&g_pos_max[i], r_pmax[tid]);
        atomicMin(&g_neg_min[i], r_nmin[tid]);
        if (offdiag) {
            int j = j0 + tid;
            atomicAdd(&g_pos_sum[j], c_psum[tid]);
            atomicAdd(&g_neg_sum[j], c_nsum[tid]);
            atomicMax(&g_pos_max[j], c_pmax[tid]);
            atomicMin(&g_neg_min[j], c_nmin[tid]);
        }
    }
}

// ---------------------------------------------------------------------------
// Kernel 5: per-row loss terms + mean. 32 blocks; one atomicAdd per block.
// ---------------------------------------------------------------------------
__global__ void finalize_kernel(float* __restrict__ out)
{
    __shared__ float red[256];
    const int tid = threadIdx.x;
    const int r   = blockIdx.x * 256 + tid;

    int   h       = g_hist[g_cls[r]];
    float cnt_p   = (float)(h - 1);
    float cnt_n   = (float)(N - h);
    float sigma_p = g_pos_sum[r] / cnt_p;
    float sigma_n = g_neg_sum[r] / cnt_n;
    float ap = __uint_as_float(g_pos_max[r]) / sigma_p + 0.5f * logf(sigma_p);
    float an = __uint_as_float(g_neg_min[r]) / sigma_n + 0.5f * logf(sigma_n);
    float lsum = fmaxf(ap - an + MARGIN, 0.f);

    red[tid] = lsum;
    __syncthreads();
    #pragma unroll
    for (int s = 128; s > 0; s >>= 1) {
        if (tid < s) red[tid] += red[tid + s];
        __syncthreads();
    }
    if (tid == 0) atomicAdd(out, red[0] * (1.f / (float)N));
}

// ---------------------------------------------------------------------------
extern "C" void kernel_launch(void* const* d_in, const int* in_sizes, int n_in,
                              void* d_out, int out_size)
{
    const float* x = (const float*)d_in[0];
    const void*  t = d_in[1];
    int tgt_elems = (n_in > 1) ? in_sizes[1] : N;

    prep_kernel<<<N / 8, 256>>>(x);
    pack_kernel<<<512, 256>>>(x, (float*)d_out);
    init2_kernel<<<(N + 255) / 256, 256>>>(t, tgt_elems);
    dist_kernel<<<dim3(64, 64), 256>>>();
    finalize_kernel<<<N / 256, 256>>>((float*)d_out);
}

// round 12
// speedup vs baseline: 1.1460x; 1.1043x over previous
#include <cuda_runtime.h>
#include <cuda_fp16.h>
#include <cstdint>

#define N 8192
#define D 128
#define NUM_CLASSES 256
#define MARGIN 0.3f

#define BM 128
#define BN 128
#define BKP 40                        // padded row: 80B = 20 banks, ldmatrix conflict-free
#define CHUNK_ELEMS (128 * BKP)       // 5120 fp16 per (rowblock, kchunk)
#define CHUNK_BYTES (CHUNK_ELEMS * 2) // 10240 B
#define STAGE_BYTES (2 * CHUNK_BYTES) // A + B chunk = 20480 B
#define SMEM_DATA   (4 * STAGE_BYTES) // all 4 k-chunks resident = 81920 B
#define SMEM_TOTAL  (SMEM_DATA + 32)  // + 4 mbarriers

// Persistent device state (module globals; no allocation).
__device__ float    g_sq[N];
__device__ int      g_cls[N];
__device__ float    g_pos_sum[N];
__device__ float    g_neg_sum[N];
__device__ unsigned g_pos_max[N];     // float bits; dsq > 0 so uint order == float order
__device__ unsigned g_neg_min[N];
__device__ int      g_hist[NUM_CLASSES];
// tile-major, pre-padded: [block 0..63][kchunk 0..3][row 0..127 * BKP + col]
__device__ __align__(16) __half g_xh[N * 4 * BKP];

__device__ __forceinline__ unsigned su32(const void* p) {
    return (unsigned)__cvta_generic_to_shared(p);
}

#define LDMX4(r0, r1, r2, r3, addr)                                         \
    asm volatile("ldmatrix.sync.aligned.m8n8.x4.shared.b16 {%0,%1,%2,%3}, [%4];" \
                 : "=r"(r0), "=r"(r1), "=r"(r2), "=r"(r3) : "r"(addr))

#define MMA_F16(c0, c1, c2, c3, a, b)                                       \
    asm volatile("mma.sync.aligned.m16n8k16.row.col.f32.f16.f16.f32 "       \
                 "{%0,%1,%2,%3}, {%4,%5,%6,%7}, {%8,%9}, {%0,%1,%2,%3};"    \
                 : "+f"(c0), "+f"(c1), "+f"(c2), "+f"(c3)                    \
                 : "r"((a)[0]), "r"((a)[1]), "r"((a)[2]), "r"((a)[3]),       \
                   "r"((b)[0]), "r"((b)[1]))

__device__ __forceinline__ void mbar_wait(unsigned mbar, unsigned parity) {
    asm volatile("{\n\t.reg .pred P;\n\t"
                 "WL%=:\n\t"
                 "mbarrier.try_wait.parity.acquire.cta.shared::cta.b64 P, [%0], %1, 0x989680;\n\t"
                 "@P bra WD%=;\n\t"
                 "bra WL%=;\n\t"
                 "WD%=:\n\t}"
                 :: "r"(mbar), "r"(parity) : "memory");
}

// ---------------------------------------------------------------------------
// Kernel 1: warp-per-row. Squared norms (fp32) + fp16 cast of X written in the
// padded tile-major layout. Also zeroes hist and out.
// ---------------------------------------------------------------------------
__global__ void prep_kernel(const float* __restrict__ x, float* __restrict__ out)
{
    int gt   = blockIdx.x * blockDim.x + threadIdx.x;
    int row  = gt >> 5;
    int lane = gt & 31;

    if (blockIdx.x == 0) {
        if (threadIdx.x < NUM_CLASSES) g_hist[threadIdx.x] = 0;
        if (threadIdx.x == 0) out[0] = 0.f;
    }
    if (row >= N) return;

    float4 v = ((const float4*)(x + (size_t)row * D))[lane];
    float s = v.x * v.x + v.y * v.y + v.z * v.z + v.w * v.w;
    #pragma unroll
    for (int o = 16; o; o >>= 1) s += __shfl_xor_sync(0xffffffffu, s, o);
    if (lane == 0) g_sq[row] = s;

    float f[4] = {v.x, v.y, v.z, v.w};
    unsigned short h[4];
    #pragma unroll
    for (int k = 0; k < 4; k++)
        h[k] = __half_as_ushort(__float2half_rn(f[k]));
    uint2 uh;
    uh.x = (unsigned)h[0] | ((unsigned)h[1] << 16);
    uh.y = (unsigned)h[2] | ((unsigned)h[3] << 16);

    int blk = row >> 7, r = row & 127;
    size_t off = (size_t)(blk * 4 + (lane >> 3)) * CHUNK_ELEMS + r * BKP + (lane & 7) * 4;
    *(uint2*)(g_xh + off) = uh;
}

// ---------------------------------------------------------------------------
// Kernel 2: targets (dtype auto-detect) + accumulator resets + histogram.
// ---------------------------------------------------------------------------
__global__ void init2_kernel(const void* __restrict__ tgt, int tgt_elems)
{
    __shared__ int s_is64;
    if (threadIdx.x == 0) {
        const long long* t64 = (const long long*)tgt;
        int is64 = 1;
        int probe = tgt_elems < 8 ? tgt_elems : 8;
        for (int i = 0; i < probe; i++) {
            long long v = t64[i];
            if (v < 0 || v >= NUM_CLASSES) { is64 = 0; break; }
        }
        s_is64 = is64;
    }
    __syncthreads();
    int r = blockIdx.x * blockDim.x + threadIdx.x;
    if (r < N) {
        int c;
        if (s_is64) c = (int)((const long long*)tgt)[r];
        else        c = ((const int*)tgt)[r];
        g_cls[r]     = c;
        g_pos_sum[r] = 0.f;
        g_neg_sum[r] = 0.f;
        g_pos_max[r] = 0u;
        g_neg_min[r] = 0x7F800000u;
        atomicAdd(&g_hist[c], 1);
    }
}

// ---------------------------------------------------------------------------
// Kernel 3: triangular tiled X*X^T, fp16 mma.sync, full-K prefetch via
// cp.async.bulk (4 chunk mbarriers, no mainloop __syncthreads).
// 256 threads, 2x4 warp grid, 64x32 warp tiles. 1D triangular grid.
// ---------------------------------------------------------------------------
__global__ __launch_bounds__(256, 2) void dist_kernel()
{
    // decode 1D triangular index -> (bx >= by)
    int t = blockIdx.x;
    int row = (int)((sqrtf(8.f * (float)t + 1.f) - 1.f) * 0.5f);
    while ((row + 1) * (row + 2) / 2 <= t) row++;
    while (row * (row + 1) / 2 > t) row--;
    const int bx = row;
    const int by = t - row * (row + 1) / 2;
    const bool offdiag = (bx != by);
    const int i0 = by * BM, j0 = bx * BN;

    extern __shared__ char smem[];
    const unsigned sbase = su32(smem);

    __shared__ float    r_psum[BM], r_nsum[BM];
    __shared__ unsigned r_pmax[BM], r_nmin[BM];
    __shared__ float    c_psum[BN], c_nsum[BN];
    __shared__ unsigned c_pmax[BN], c_nmin[BN];
    __shared__ float    s_sqi[BM], s_sqj[BN];
    __shared__ int      s_clsi[BM], s_clsj[BN];

    const int tid = threadIdx.x;
    const int wid = tid >> 5, lane = tid & 31;
    const int warp_m = (wid >> 2) * 64;   // 0 or 64
    const int warp_n = (wid & 3) * 32;    // 0,32,64,96

    if (tid < BM) {
        r_psum[tid] = 0.f; r_nsum[tid] = 0.f; r_pmax[tid] = 0u; r_nmin[tid] = 0x7F800000u;
        c_psum[tid] = 0.f; c_nsum[tid] = 0.f; c_pmax[tid] = 0u; c_nmin[tid] = 0x7F800000u;
        s_sqi[tid]  = g_sq[i0 + tid];
        s_clsi[tid] = g_cls[i0 + tid];
    } else {
        int c = tid - BM;
        s_sqj[c]  = g_sq[j0 + c];
        s_clsj[c] = g_cls[j0 + c];
    }
    if (tid == 0) {
        #pragma unroll
        for (int kb = 0; kb < 4; kb++)
            asm volatile("mbarrier.init.shared.b64 [%0], %1;"
                         :: "r"(sbase + SMEM_DATA + kb * 8), "r"(1u) : "memory");
    }
    __syncthreads();

    if (tid == 0) {
        #pragma unroll
        for (int kb = 0; kb < 4; kb++) {
            unsigned mbar = sbase + SMEM_DATA + kb * 8;
            asm volatile("mbarrier.arrive.expect_tx.shared.b64 _, [%0], %1;"
                         :: "r"(mbar), "r"((unsigned)STAGE_BYTES) : "memory");
            const __half* srcA = g_xh + (size_t)(by * 4 + kb) * CHUNK_ELEMS;
            const __half* srcB = g_xh + (size_t)(bx * 4 + kb) * CHUNK_ELEMS;
            unsigned dstA = sbase + (unsigned)kb * STAGE_BYTES;
            asm volatile("cp.async.bulk.shared::cluster.global.mbarrier::complete_tx::bytes "
                         "[%0], [%1], %2, [%3];"
                         :: "r"(dstA), "l"(srcA), "r"((unsigned)CHUNK_BYTES), "r"(mbar)
                         : "memory");
            asm volatile("cp.async.bulk.shared::cluster.global.mbarrier::complete_tx::bytes "
                         "[%0], [%1], %2, [%3];"
                         :: "r"(dstA + CHUNK_BYTES), "l"(srcB), "r"((unsigned)CHUNK_BYTES), "r"(mbar)
                         : "memory");
        }
    }

    float C[8][8];
    #pragma unroll
    for (int a = 0; a < 8; a++)
        #pragma unroll
        for (int b = 0; b < 8; b++) C[a][b] = 0.f;

    // per-lane ldmatrix byte offsets (80B row pitch)
    const unsigned aoff = (unsigned)(lane & 15) * (BKP * 2) + (unsigned)(lane >> 4) * 16
                        + (unsigned)warp_m * (BKP * 2);
    const unsigned boff = (unsigned)(((lane >> 4) & 1) * 8 + (lane & 7)) * (BKP * 2)
                        + (unsigned)((lane >> 3) & 1) * 16
                        + (unsigned)warp_n * (BKP * 2);

    #pragma unroll
    for (int kb = 0; kb < 4; kb++) {
        mbar_wait(sbase + SMEM_DATA + kb * 8, 0u);

        const unsigned sb = sbase + (unsigned)kb * STAGE_BYTES;
        const unsigned aA = sb + aoff;
        const unsigned aB = sb + CHUNK_BYTES + boff;

        #pragma unroll
        for (int ks = 0; ks < 2; ks++) {
            const unsigned kbyte = (unsigned)ks * 32;  // 16 fp16 = 32B
            unsigned A[4][4], B[4][2];
            #pragma unroll
            for (int mt = 0; mt < 4; mt++) {
                const unsigned moff = (unsigned)(mt * 16) * (BKP * 2) + kbyte;
                LDMX4(A[mt][0], A[mt][1], A[mt][2], A[mt][3], aA + moff);
            }
            #pragma unroll
            for (int bq = 0; bq < 2; bq++) {
                const unsigned noff = (unsigned)(bq * 16) * (BKP * 2) + kbyte;
                unsigned r0, r1, r2, r3;
                LDMX4(r0, r1, r2, r3, aB + noff);
                B[2 * bq][0] = r0; B[2 * bq][1] = r1;
                B[2 * bq + 1][0] = r2; B[2 * bq + 1][1] = r3;
            }
            #pragma unroll
            for (int mt = 0; mt < 4; mt++)
                #pragma unroll
                for (int nt = 0; nt < 4; nt++)
                    MMA_F16(C[2*mt][2*nt], C[2*mt][2*nt+1], C[2*mt+1][2*nt], C[2*mt+1][2*nt+1],
                            A[mt], B[nt]);
        }
    }

    // ---- epilogue (metadata from smem) ----
    const int rg = lane >> 2, cg = lane & 3;

    // row pass: convert dot->dsq in place, reduce this thread's 8 cols, quad shuffle
    #pragma unroll
    for (int mi = 0; mi < 8; mi++) {
        const int lr   = warp_m + (mi >> 1) * 16 + (mi & 1) * 8 + rg;
        const float si = s_sqi[lr];
        const int   ki = s_clsi[lr];
        const int   gi = i0 + lr;
        float psum = 0.f, nsum = 0.f;
        float pmax = 0.f, nmin = __uint_as_float(0x7F800000u);
        #pragma unroll
        for (int ci = 0; ci < 8; ci++) {
            const int lc = warp_n + (ci >> 1) * 8 + 2 * cg + (ci & 1);
            float dsq = fmaxf(si + s_sqj[lc] - 2.f * C[mi][ci], 1e-12f);
            C[mi][ci] = dsq;
            if (ki == s_clsj[lc]) {
                if (gi != j0 + lc) {       // reference drops the self element
                    psum += dsq;
                    pmax  = fmaxf(pmax, dsq);
                }
            } else {
                nsum += dsq;
                nmin  = fminf(nmin, dsq);
            }
        }
        #pragma unroll
        for (int o = 1; o <= 2; o <<= 1) {
            psum += __shfl_xor_sync(0xffffffffu, psum, o);
            nsum += __shfl_xor_sync(0xffffffffu, nsum, o);
            pmax  = fmaxf(pmax, __shfl_xor_sync(0xffffffffu, pmax, o));
            nmin  = fminf(nmin, __shfl_xor_sync(0xffffffffu, nmin, o));
        }
        if (cg == 0) {
            atomicAdd(&r_psum[lr], psum);
            atomicAdd(&r_nsum[lr], nsum);
            atomicMax(&r_pmax[lr], __float_as_uint(pmax));
            atomicMin(&r_nmin[lr], __float_as_uint(nmin));
        }
    }

    // column pass (symmetry: row-j reductions) for off-diagonal tiles
    if (offdiag) {
        #pragma unroll
        for (int ci = 0; ci < 8; ci++) {
            const int lc = warp_n + (ci >> 1) * 8 + 2 * cg + (ci & 1);
            const int kj = s_clsj[lc];
            float psum = 0.f, nsum = 0.f;
            float pmax = 0.f, nmin = __uint_as_float(0x7F800000u);
            #pragma unroll
            for (int mi = 0; mi < 8; mi++) {
                const int lr = warp_m + (mi >> 1) * 16 + (mi & 1) * 8 + rg;
                float dsq = C[mi][ci];
                if (s_clsi[lr] == kj) {
                    psum += dsq;
                    pmax  = fmaxf(pmax, dsq);
                } else {
                    nsum += dsq;
                    nmin  = fminf(nmin, dsq);
                }
            }
            #pragma unroll
            for (int o = 4; o <= 16; o <<= 1) {
                psum += __shfl_xor_sync(0xffffffffu, psum, o);
                nsum += __shfl_xor_sync(0xffffffffu, nsum, o);
                pmax  = fmaxf(pmax, __shfl_xor_sync(0xffffffffu, pmax, o));
                nmin  = fminf(nmin, __shfl_xor_sync(0xffffffffu, nmin, o));
            }
            if (lane < 4) {
                atomicAdd(&c_psum[lc], psum);
                atomicAdd(&c_nsum[lc], nsum);
                atomicMax(&c_pmax[lc], __float_as_uint(pmax));
                atomicMin(&c_nmin[lc], __float_as_uint(nmin));
            }
        }
    }

    __syncthreads();
    if (tid < BM) {
        int i = i0 + tid;
        atomicAdd(&g_pos_sum[i], r_psum[tid]);
        atomicAdd(&g_neg_sum[i], r_nsum[tid]);
        atomicMax(&g_pos_max[i], r_pmax[tid]);
        atomicMin(&g_neg_min[i], r_nmin[tid]);
        if (offdiag) {
            int j = j0 + tid;
            atomicAdd(&g_pos_sum[j], c_psum[tid]);
            atomicAdd(&g_neg_sum[j], c_nsum[tid]);
            atomicMax(&g_pos_max[j], c_pmax[tid]);
            atomicMin(&g_neg_min[j], c_nmin[tid]);
        }
    }
}

// ---------------------------------------------------------------------------
// Kernel 4: per-row loss terms + mean. 32 blocks; one atomicAdd per block.
// ---------------------------------------------------------------------------
__global__ void finalize_kernel(float* __restrict__ out)
{
    __shared__ float red[256];
    const int tid = threadIdx.x;
    const int r   = blockIdx.x * 256 + tid;

    int   h       = g_hist[g_cls[r]];
    float cnt_p   = (float)(h - 1);
    float cnt_n   = (float)(N - h);
    float sigma_p = g_pos_sum[r] / cnt_p;
    float sigma_n = g_neg_sum[r] / cnt_n;
    float ap = __uint_as_float(g_pos_max[r]) / sigma_p + 0.5f * logf(sigma_p);
    float an = __uint_as_float(g_neg_min[r]) / sigma_n + 0.5f * logf(sigma_n);
    float lsum = fmaxf(ap - an + MARGIN, 0.f);

    red[tid] = lsum;
    __syncthreads();
    #pragma unroll
    for (int s = 128; s > 0; s >>= 1) {
        if (tid < s) red[tid] += red[tid + s];
        __syncthreads();
    }
    if (tid == 0) atomicAdd(out, red[0] * (1.f / (float)N));
}

// ---------------------------------------------------------------------------
extern "C" void kernel_launch(void* const* d_in, const int* in_sizes, int n_in,
                              void* d_out, int out_size)
{
    const float* x = (const float*)d_in[0];
    const void*  t = d_in[1];
    int tgt_elems = (n_in > 1) ? in_sizes[1] : N;

    cudaFuncSetAttribute(dist_kernel, cudaFuncAttributeMaxDynamicSharedMemorySize,
                         SMEM_TOTAL);

    prep_kernel<<<N / 8, 256>>>(x, (float*)d_out);
    init2_kernel<<<(N + 255) / 256, 256>>>(t, tgt_elems);
    dist_kernel<<<2080, 256, SMEM_TOTAL>>>();
    finalize_kernel<<<N / 256, 256>>>((float*)d_out);
}